// round 3
// baseline (speedup 1.0000x reference)
#include <cuda_runtime.h>
#include <stdint.h>

// carry_save_adder: exact-binary reduction, TMA-bulk pipelined.
// S_b = sum over kept i of value(x[b,i,:]); out bits = S_b & 0xFFFF, carry = S_b >> 16.
// Persistent CTAs grid-stride over 32KB tiles (8 rows of 4KB), double-buffered
// in smem via cp.async.bulk + mbarrier. One warp per row consumes from smem.

#define TILE_ROWS   8
#define ROW_FLOATS  1024                        // 64 values * 16 bits
#define TILE_BYTES  (TILE_ROWS * ROW_FLOATS * 4) // 32768
#define STAGES      2
#define NCTA        456                          // 3 per SM on 152-SM GB300

__device__ __forceinline__ void mbar_init(uint32_t mbar, uint32_t count) {
    asm volatile("mbarrier.init.shared::cta.b64 [%0], %1;" :: "r"(mbar), "r"(count) : "memory");
}
__device__ __forceinline__ void mbar_expect_tx(uint32_t mbar, uint32_t bytes) {
    asm volatile("mbarrier.arrive.expect_tx.shared::cta.b64 _, [%0], %1;"
                 :: "r"(mbar), "r"(bytes) : "memory");
}
__device__ __forceinline__ void bulk_copy_g2s(uint32_t dst_smem, const void* src, uint32_t bytes, uint32_t mbar) {
    asm volatile("cp.async.bulk.shared::cta.global.mbarrier::complete_tx::bytes [%0], [%1], %2, [%3];"
                 :: "r"(dst_smem), "l"(src), "r"(bytes), "r"(mbar) : "memory");
}
__device__ __forceinline__ void mbar_wait(uint32_t mbar, uint32_t parity) {
    uint32_t done;
    asm volatile(
        "{\n\t.reg .pred p;\n\t"
        "mbarrier.try_wait.parity.acquire.cta.shared::cta.b64 p, [%1], %2;\n\t"
        "selp.b32 %0, 1, 0, p;\n\t}"
        : "=r"(done) : "r"(mbar), "r"(parity) : "memory");
    if (!done) {
        asm volatile(
            "{\n\t.reg .pred P1;\n\t"
            "WL_%=:\n\t"
            "mbarrier.try_wait.parity.acquire.cta.shared::cta.b64 P1, [%0], %1, 0x989680;\n\t"
            "@P1 bra.uni WD_%=;\n\t"
            "bra.uni WL_%=;\n\t"
            "WD_%=:\n\t}"
            :: "r"(mbar), "r"(parity) : "memory");
    }
}

__global__ void __launch_bounds__(256)
csa_tma_kernel(const float* __restrict__ x, const int* __restrict__ mask,
               float* __restrict__ out, int B)
{
    extern __shared__ __align__(128) unsigned char smem[];
    float*    tiles = (float*)smem;                                // STAGES * 8192 floats
    uint32_t  mbar0 = (uint32_t)__cvta_generic_to_shared(smem + STAGES * TILE_BYTES);

    const unsigned FULL = 0xFFFFFFFFu;
    const int tid  = threadIdx.x;
    const int lane = tid & 31;
    const int wib  = tid >> 5;                                     // warp-in-block = row-in-tile
    const int ntiles = B / TILE_ROWS;

    if (tid == 0) {
        mbar_init(mbar0,     1);
        mbar_init(mbar0 + 8, 1);
    }
    __syncthreads();

    // Keep mask over the 64 values (indices 0,1 always kept), per-warp ballot.
    const unsigned mb_lo = __ballot_sync(FULL, mask[lane]      > 0) | 3u;
    const unsigned mb_hi = __ballot_sync(FULL, mask[lane + 32] > 0);
    const unsigned q = (unsigned)lane >> 2;
    float keepf[8];
    #pragma unroll
    for (int t = 0; t < 8; ++t) {
        unsigned bit = (t < 4) ? ((mb_lo >> (8 * t + q)) & 1u)
                               : ((mb_hi >> (8 * (t - 4) + q)) & 1u);
        keepf[t] = bit ? 1.0f : 0.0f;
    }
    const float wgt = __int_as_float((127 + (((int)lane & 3) << 2)) << 23); // 2^((lane&3)*4)

    // Prologue: issue first STAGES tiles.
    if (tid == 0) {
        #pragma unroll
        for (int k = 0; k < STAGES; ++k) {
            long t = (long)blockIdx.x + (long)k * gridDim.x;
            if (t < ntiles) {
                mbar_expect_tx(mbar0 + 8 * k, TILE_BYTES);
                bulk_copy_g2s((uint32_t)__cvta_generic_to_shared(tiles + k * (TILE_BYTES / 4)),
                              x + t * (TILE_BYTES / 4), TILE_BYTES, mbar0 + 8 * k);
            }
        }
    }

    int j = 0;
    for (long t = blockIdx.x; t < ntiles; t += gridDim.x, ++j) {
        const int s  = j & 1;
        const int ph = (j >> 1) & 1;
        mbar_wait(mbar0 + 8 * s, (uint32_t)ph);

        const float4* row = (const float4*)tiles + s * (TILE_BYTES / 16) + wib * (ROW_FLOATS / 4);

        float4 v[8];
        #pragma unroll
        for (int tt = 0; tt < 8; ++tt)
            v[tt] = row[lane + (tt << 5)];

        float sumf = 0.0f;
        #pragma unroll
        for (int tt = 0; tt < 8; ++tt) {
            float part = v[tt].x;
            part = fmaf(v[tt].y, 2.0f, part);
            part = fmaf(v[tt].z, 4.0f, part);
            part = fmaf(v[tt].w, 8.0f, part);
            sumf = fmaf(part, keepf[tt], sumf);
        }
        sumf *= wgt;

        #pragma unroll
        for (int off = 16; off; off >>= 1)
            sumf += __shfl_xor_sync(FULL, sumf, off);

        const unsigned ss = (unsigned)sumf;
        const long grow = t * TILE_ROWS + wib;
        if (lane < 16)
            out[grow * 16 + lane] = (float)((ss >> lane) & 1u);
        else if (lane == 16)
            out[(long)B * 16 + grow] = (float)(ss >> 16);

        __syncthreads();   // everyone done reading stage s

        if (tid == 0) {
            long tn = t + (long)STAGES * gridDim.x;
            if (tn < ntiles) {
                mbar_expect_tx(mbar0 + 8 * s, TILE_BYTES);
                bulk_copy_g2s((uint32_t)__cvta_generic_to_shared(tiles + s * (TILE_BYTES / 4)),
                              x + tn * (TILE_BYTES / 4), TILE_BYTES, mbar0 + 8 * s);
            }
        }
    }
}

extern "C" void kernel_launch(void* const* d_in, const int* in_sizes, int n_in,
                              void* d_out, int out_size)
{
    const float* x   = (const float*)d_in[0];   // (B, 64, 16) float32
    const int*   msk = (const int*)d_in[1];     // (64,) int32
    float*       out = (float*)d_out;           // B*16 output bits, then B carries

    int B = in_sizes[0] / 1024;

    const int smem_bytes = STAGES * TILE_BYTES + 2 * 8;  // tiles + 2 mbarriers
    cudaFuncSetAttribute(csa_tma_kernel, cudaFuncAttributeMaxDynamicSharedMemorySize, smem_bytes);

    int ntiles = B / TILE_ROWS;
    int grid = NCTA < ntiles ? NCTA : ntiles;
    csa_tma_kernel<<<grid, 256, smem_bytes>>>(x, msk, out, B);
}

// round 4
// speedup vs baseline: 1.0932x; 1.0932x over previous
#include <cuda_runtime.h>
#include <stdint.h>

// carry_save_adder: exact-binary reduction.
// S_b = sum over kept i of value(x[b,i,:]); out bits = S_b & 0xFFFF, carry = S_b >> 16.
// Persistent grid (1 wave, 4 CTAs/SM, 64-reg budget): one warp per row,
// 8 front-batched LDG.128 (evict-first), FFMA-imm bit-weighting with the
// loop-invariant nibble weight 2^((lane&3)*4) factored out, exact fp32 sums.

__global__ void __launch_bounds__(256, 4)
csa_kernel(const float4* __restrict__ x, const int* __restrict__ mask,
           float* __restrict__ out, int B)
{
    const unsigned FULL = 0xFFFFFFFFu;
    const int lane = threadIdx.x & 31;
    const int w0   = (blockIdx.x << 3) + (threadIdx.x >> 5);  // global warp id
    const int nw   = gridDim.x << 3;                           // total warps

    // Keep mask over the 64 values (indices 0,1 always kept).
    const unsigned mb_lo = __ballot_sync(FULL, mask[lane]      > 0) | 3u;
    const unsigned mb_hi = __ballot_sync(FULL, mask[lane + 32] > 0);
    const bool allkeep = (mb_lo == 0xFFFFFFFFu) & (mb_hi == 0xFFFFFFFFu);

    // Per-thread nibble weight 2^((lane&3)*4), loop-invariant.
    const float wgt = __int_as_float((127 + (((int)lane & 3) << 2)) << 23);

    if (allkeep) {
        // ---- fast path: no masking ----
        for (int row = w0; row < B; row += nw) {
            const float4* r = x + (size_t)row * 256;
            float4 v[8];
            #pragma unroll
            for (int t = 0; t < 8; ++t)
                v[t] = __ldcs(&r[lane + (t << 5)]);

            float p[8];
            #pragma unroll
            for (int t = 0; t < 8; ++t) {
                float part = v[t].x;
                part = fmaf(v[t].y, 2.0f, part);
                part = fmaf(v[t].z, 4.0f, part);
                part = fmaf(v[t].w, 8.0f, part);
                p[t] = part;
            }
            // pairwise tree (short dependency chain)
            float s01 = p[0] + p[1], s23 = p[2] + p[3];
            float s45 = p[4] + p[5], s67 = p[6] + p[7];
            float sumf = ((s01 + s23) + (s45 + s67)) * wgt;

            #pragma unroll
            for (int off = 16; off; off >>= 1)
                sumf += __shfl_xor_sync(FULL, sumf, off);

            const unsigned s = (unsigned)sumf;
            if (lane < 16)
                out[(size_t)row * 16 + lane] = (float)((s >> lane) & 1u);
            else if (lane == 16)
                out[(size_t)B * 16 + row] = (float)(s >> 16);
        }
    } else {
        // ---- generic path: per-chunk keep weights ----
        const unsigned q = (unsigned)lane >> 2;
        float keepf[8];
        #pragma unroll
        for (int t = 0; t < 8; ++t) {
            unsigned bit = (t < 4) ? ((mb_lo >> (8 * t + q)) & 1u)
                                   : ((mb_hi >> (8 * (t - 4) + q)) & 1u);
            keepf[t] = bit ? 1.0f : 0.0f;
        }
        for (int row = w0; row < B; row += nw) {
            const float4* r = x + (size_t)row * 256;
            float4 v[8];
            #pragma unroll
            for (int t = 0; t < 8; ++t)
                v[t] = __ldcs(&r[lane + (t << 5)]);

            float sumf = 0.0f;
            #pragma unroll
            for (int t = 0; t < 8; ++t) {
                float part = v[t].x;
                part = fmaf(v[t].y, 2.0f, part);
                part = fmaf(v[t].z, 4.0f, part);
                part = fmaf(v[t].w, 8.0f, part);
                sumf = fmaf(part, keepf[t], sumf);
            }
            sumf *= wgt;

            #pragma unroll
            for (int off = 16; off; off >>= 1)
                sumf += __shfl_xor_sync(FULL, sumf, off);

            const unsigned s = (unsigned)sumf;
            if (lane < 16)
                out[(size_t)row * 16 + lane] = (float)((s >> lane) & 1u);
            else if (lane == 16)
                out[(size_t)B * 16 + row] = (float)(s >> 16);
        }
    }
}

extern "C" void kernel_launch(void* const* d_in, const int* in_sizes, int n_in,
                              void* d_out, int out_size)
{
    const float4* x   = (const float4*)d_in[0];   // (B, 64, 16) float32
    const int*    msk = (const int*)d_in[1];      // (64,) int32
    float*        out = (float*)d_out;            // B*16 output bits, then B carries

    int B = in_sizes[0] / 1024;                   // 64*16 floats per batch row

    // Persistent single wave: 4 CTAs/SM on 152 SMs.
    int grid = 152 * 4;
    int maxg = (B + 7) / 8;
    if (grid > maxg) grid = maxg;
    csa_kernel<<<grid, 256>>>(x, msk, out, B);
}